// round 16
// baseline (speedup 1.0000x reference)
#include <cuda_runtime.h>
#include <cuda_bf16.h>
#include <math.h>

// ---------------- problem constants ----------------
#define BATCH   16
#define CIN     256
#define IMGH    64
#define IMGW    64
#define NPIX    4096
#define HEADS   4
#define DK      16
#define DV      64
#define RKS     7
#define TAPS    49
#define PADR    3

#define N_OUT   144
#define MT      128
#define KCH     64
#define NCHK    32        // pixel chunks per batch (= k_proj grid.x)

#define PITCH_A 272
#define PITCH_B 144
#define OFF_AHI 0
#define OFF_ALO (OFF_AHI + KCH * PITCH_A)
#define OFF_BHI (OFF_ALO + KCH * PITCH_A)
#define OFF_BLO (OFF_BHI + N_OUT * PITCH_B)
#define STAGE_BYTES (OFF_BLO + N_OUT * PITCH_B)      // 76288
#define DPITCH  132
#define W_OFF   STAGE_BYTES                          // w_sm region (after staging dies)
#define SM_PROJ (W_OFF + 16 * DPITCH * 4 + 64)       // + m_sm

// ---------------- device scratch ----------------
__device__ float g_q[BATCH * 64 * NPIX];
__device__ float g_k[BATCH * 16 * NPIX];
__device__ float g_v[BATCH * 64 * NPIX];
__device__ float g_sq[64], g_bq[64];
__device__ float g_sv[64], g_bv[64];
__device__ float g_lamc[BATCH * 16 * 64];
__device__ float g_psum[128][512];
__device__ float g_psq [128][512];
__device__ __nv_bfloat16 g_wbh[N_OUT * CIN];
__device__ __nv_bfloat16 g_wbl[N_OUT * CIN];
__device__ float g_pm  [BATCH][NCHK][16];        // per-chunk local k max
__device__ float g_pz  [BATCH][NCHK][16];        // per-chunk z partial (local-max scaled)
__device__ float g_plam[BATCH][NCHK][16][64];    // per-chunk lam partial

// ---------------- helpers ----------------
__device__ __forceinline__ unsigned smem_u32(const void* p) {
    unsigned a;
    asm("{ .reg .u64 t; cvta.to.shared.u64 t, %1; cvt.u32.u64 %0, t; }" : "=r"(a) : "l"(p));
    return a;
}
__device__ __forceinline__ void ldsm_x4t(unsigned addr, unsigned& r0, unsigned& r1,
                                         unsigned& r2, unsigned& r3) {
    asm volatile("ldmatrix.sync.aligned.m8n8.x4.trans.shared.b16 {%0,%1,%2,%3}, [%4];"
                 : "=r"(r0), "=r"(r1), "=r"(r2), "=r"(r3) : "r"(addr));
}
__device__ __forceinline__ void ldsm_x2(unsigned addr, unsigned& r0, unsigned& r1) {
    asm volatile("ldmatrix.sync.aligned.m8n8.x2.shared.b16 {%0,%1}, [%2];"
                 : "=r"(r0), "=r"(r1) : "r"(addr));
}
__device__ __forceinline__ void mma16816(float* d, const unsigned* a, unsigned b0, unsigned b1) {
    asm volatile(
        "mma.sync.aligned.m16n8k16.row.col.f32.bf16.bf16.f32 "
        "{%0,%1,%2,%3}, {%4,%5,%6,%7}, {%8,%9}, {%0,%1,%2,%3};"
        : "+f"(d[0]), "+f"(d[1]), "+f"(d[2]), "+f"(d[3])
        : "r"(a[0]), "r"(a[1]), "r"(a[2]), "r"(a[3]), "r"(b0), "r"(b1));
}
__device__ __forceinline__ void bf_split(float f, unsigned short& hi, unsigned short& lo) {
    __nv_bfloat16 h = __float2bfloat16_rn(f);
    __nv_bfloat16 l = __float2bfloat16_rn(f - __bfloat162float(h));
    hi = __bfloat16_as_ushort(h);
    lo = __bfloat16_as_ushort(l);
}

// ======================================================================
// K0: one-time W -> bf16 hi/lo split.
// ======================================================================
__global__ __launch_bounds__(256)
void k_wconv(const float* __restrict__ Wq, const float* __restrict__ Wk,
             const float* __restrict__ Wv) {
    int idx = blockIdx.x * 256 + threadIdx.x;
    if (idx >= (N_OUT * CIN) / 4) return;
    int o  = idx >> 6;
    int c4 = (idx & 63) * 4;
    const float* wrow = (o < 64) ? (Wq + o * CIN)
                      : (o < 80) ? (Wk + (o - 64) * CIN)
                                 : (Wv + (o - 80) * CIN);
    float4 w = *(const float4*)(wrow + c4);
    unsigned short h[4], l[4];
    bf_split(w.x, h[0], l[0]);
    bf_split(w.y, h[1], l[1]);
    bf_split(w.z, h[2], l[2]);
    bf_split(w.w, h[3], l[3]);
    unsigned long long hp = (unsigned long long)h[0] | ((unsigned long long)h[1] << 16)
                          | ((unsigned long long)h[2] << 32) | ((unsigned long long)h[3] << 48);
    unsigned long long lp = (unsigned long long)l[0] | ((unsigned long long)l[1] << 16)
                          | ((unsigned long long)l[2] << 32) | ((unsigned long long)l[3] << 48);
    *(unsigned long long*)(g_wbh + o * CIN + c4) = hp;
    *(unsigned long long*)(g_wbl + o * CIN + c4) = lp;
}

// ======================================================================
// K1: projection (HMMA bf16 2-way split) + BN-stat partials + FUSED
// lambda_c partials (flash-softmax with per-chunk local max).
// ======================================================================
__global__ __launch_bounds__(256)
void k_proj(const float* __restrict__ x) {
    extern __shared__ __align__(16) char smem[];
    const unsigned sb = smem_u32(smem);
    const int tid  = threadIdx.x;
    const int lane = tid & 31;
    const int wid  = tid >> 5;
    const int wm   = wid & 3;
    const int wn   = wid >> 2;
    const int b    = blockIdx.y;
    const int pix0 = blockIdx.x * MT;

    const float* xb = x + (size_t)b * CIN * NPIX + pix0;

    float acc[2][9][4];
#pragma unroll
    for (int mi = 0; mi < 2; ++mi)
#pragma unroll
        for (int ni = 0; ni < 9; ++ni)
#pragma unroll
            for (int r = 0; r < 4; ++r) acc[mi][ni][r] = 0.f;

    const int a_kl = (lane & 7) + ((lane >> 4) << 3);
    const int a_pl = ((lane >> 3) & 1) * 8;
    const int l15  = lane & 15;
    const int b_nl = l15 & 7;
    const int b_kl = ((l15 >> 3) & 1) * 8;

    for (int chunk = 0; chunk < 4; ++chunk) {
        const int c0 = chunk * KCH;

#pragma unroll
        for (int i = 0; i < 8; ++i) {
            int idx = tid + i * 256;
            int cc = idx >> 5, pq = idx & 31;
            float4 xv = *(const float4*)(xb + (size_t)(c0 + cc) * NPIX + pq * 4);
            unsigned short h[4], l[4];
            bf_split(xv.x, h[0], l[0]);
            bf_split(xv.y, h[1], l[1]);
            bf_split(xv.z, h[2], l[2]);
            bf_split(xv.w, h[3], l[3]);
            uint2 hp = make_uint2((unsigned)h[0] | ((unsigned)h[1] << 16),
                                  (unsigned)h[2] | ((unsigned)h[3] << 16));
            uint2 lp = make_uint2((unsigned)l[0] | ((unsigned)l[1] << 16),
                                  (unsigned)l[2] | ((unsigned)l[3] << 16));
            *(uint2*)(smem + OFF_AHI + cc * PITCH_A + pq * 8) = hp;
            *(uint2*)(smem + OFF_ALO + cc * PITCH_A + pq * 8) = lp;
        }
#pragma unroll
        for (int i = 0; i < 5; ++i) {
            int idx = tid + i * 256;
            if (idx < 1152) {
                int o = idx >> 3, j = idx & 7;
                float4 h4 = *(const float4*)((const char*)g_wbh + (o * CIN + c0) * 2 + j * 16);
                float4 l4 = *(const float4*)((const char*)g_wbl + (o * CIN + c0) * 2 + j * 16);
                *(float4*)(smem + OFF_BHI + o * PITCH_B + j * 16) = h4;
                *(float4*)(smem + OFF_BLO + o * PITCH_B + j * 16) = l4;
            }
        }
        __syncthreads();

#pragma unroll
        for (int ks = 0; ks < 4; ++ks) {
            unsigned ahi[2][4], alo[2][4];
#pragma unroll
            for (int mi = 0; mi < 2; ++mi) {
                unsigned aoff = (unsigned)((ks * 16 + a_kl) * PITCH_A
                                           + (wm * 32 + mi * 16 + a_pl) * 2);
                ldsm_x4t(sb + OFF_AHI + aoff, ahi[mi][0], ahi[mi][1], ahi[mi][2], ahi[mi][3]);
                ldsm_x4t(sb + OFF_ALO + aoff, alo[mi][0], alo[mi][1], alo[mi][2], alo[mi][3]);
            }
#pragma unroll
            for (int ni = 0; ni < 9; ++ni) {
                unsigned boff = (unsigned)((wn * 72 + ni * 8 + b_nl) * PITCH_B
                                           + (ks * 16 + b_kl) * 2);
                unsigned bh0, bh1, bl0, bl1;
                ldsm_x2(sb + OFF_BHI + boff, bh0, bh1);
                ldsm_x2(sb + OFF_BLO + boff, bl0, bl1);
#pragma unroll
                for (int mi = 0; mi < 2; ++mi) {
                    mma16816(acc[mi][ni], ahi[mi], bh0, bh1);
                    mma16816(acc[mi][ni], ahi[mi], bl0, bl1);
                    mma16816(acc[mi][ni], alo[mi], bh0, bh1);
                }
            }
        }
        __syncthreads();
    }

    // ---- epilogue: fragments -> smem D[o][pix] ----
    float* dsm  = (float*)smem;
    float* w_sm = (float*)(smem + W_OFF);          // [16 kk][DPITCH]
    float* m_sm = w_sm + 16 * DPITCH;              // [16]
#pragma unroll
    for (int mi = 0; mi < 2; ++mi)
#pragma unroll
        for (int ni = 0; ni < 9; ++ni) {
            int o = wn * 72 + ni * 8 + (lane & 3) * 2;
            int p = wm * 32 + mi * 16 + (lane >> 2);
            dsm[o * DPITCH + p]           = acc[mi][ni][0];
            dsm[(o + 1) * DPITCH + p]     = acc[mi][ni][1];
            dsm[o * DPITCH + p + 8]       = acc[mi][ni][2];
            dsm[(o + 1) * DPITCH + p + 8] = acc[mi][ni][3];
        }
    __syncthreads();

    // ---- global q/k/v stores ----
    float* qd = g_q + (size_t)b * 64 * NPIX;
    float* kd = g_k + (size_t)b * 16 * NPIX;
    float* vd = g_v + (size_t)b * 64 * NPIX;
#pragma unroll
    for (int i = 0; i < 18; ++i) {
        int idx = tid + i * 256;
        int o = idx >> 5, p4 = idx & 31;
        float4 val = *(const float4*)(dsm + o * DPITCH + p4 * 4);
        float* dst;
        if (o < 64)      dst = qd + (size_t)o * NPIX;
        else if (o < 80) dst = kd + (size_t)(o - 64) * NPIX;
        else             dst = vd + (size_t)(o - 80) * NPIX;
        *(float4*)(dst + pix0 + p4 * 4) = val;
    }

    // ---- BN-stat partials (q + v channels) & local k-row max ----
    if (tid < N_OUT) {
        const int o = tid;
        const float* row = dsm + o * DPITCH;
        if (o >= 64 && o < 80) {
            float m = -1e30f;
#pragma unroll
            for (int j = 0; j < 128; j += 4) {
                float4 v = *(const float4*)(row + j);
                m = fmaxf(m, fmaxf(fmaxf(v.x, v.y), fmaxf(v.z, v.w)));
            }
            m_sm[o - 64] = m;
            g_pm[b][blockIdx.x][o - 64] = m;
        } else {
            float s = 0.f, s2 = 0.f;
#pragma unroll
            for (int j = 0; j < 128; j += 4) {
                float4 v = *(const float4*)(row + j);
                s  += v.x + v.y + v.z + v.w;
                s2 += v.x * v.x + v.y * v.y + v.z * v.z + v.w * v.w;
            }
            int ch = (o < 64) ? o : (o - 16);
            int slot = b * 32 + blockIdx.x;
            g_psum[ch][slot] = s;
            g_psq [ch][slot] = s2;
        }
    }
    __syncthreads();

    // ---- w = exp(k - m_local) ----
#pragma unroll
    for (int i = 0; i < 8; ++i) {
        int idx = tid + i * 256;               // 0..2047
        int kk = idx >> 7, p = idx & 127;
        w_sm[kk * DPITCH + p] = expf(dsm[(64 + kk) * DPITCH + p] - m_sm[kk]);
    }
    __syncthreads();

    // ---- z partials: 8 warps x 2 kk ----
    {
#pragma unroll
        for (int kk = wid; kk < 16; kk += 8) {
            float s = 0.f;
#pragma unroll
            for (int p = lane; p < 128; p += 32) s += w_sm[kk * DPITCH + p];
#pragma unroll
            for (int o = 16; o > 0; o >>= 1) s += __shfl_down_sync(0xffffffffu, s, o);
            if (lane == 0) g_pz[b][blockIdx.x][kk] = s;
        }
    }

    // ---- lam partials: thread (kk, vq) -> v channels vq + 16m ----
    {
        const int kk = tid >> 4;
        const int vq = tid & 15;
        float la[4] = {0.f, 0.f, 0.f, 0.f};
#pragma unroll
        for (int p4 = 0; p4 < 32; ++p4) {
            float4 w4 = *(const float4*)(w_sm + kk * DPITCH + p4 * 4);
#pragma unroll
            for (int m = 0; m < 4; ++m) {
                float4 v4 = *(const float4*)(dsm + (80 + vq + 16 * m) * DPITCH + p4 * 4);
                la[m] += w4.x * v4.x + w4.y * v4.y + w4.z * v4.z + w4.w * v4.w;
            }
        }
#pragma unroll
        for (int m = 0; m < 4; ++m)
            g_plam[b][blockIdx.x][kk][vq + 16 * m] = la[m];
    }
}

// ======================================================================
// K2: reduce BN-stat partials -> fold params. 128 blocks.
// ======================================================================
__global__ __launch_bounds__(128)
void k_reduce(const float* __restrict__ gamma_q, const float* __restrict__ beta_q,
              const float* __restrict__ gamma_v, const float* __restrict__ beta_v) {
    const int ch  = blockIdx.x;
    const int tid = threadIdx.x;

    float s = 0.f, s2 = 0.f;
#pragma unroll
    for (int i = tid; i < 512; i += 128) { s += g_psum[ch][i]; s2 += g_psq[ch][i]; }
    __shared__ float ss[128], ss2[128];
    ss[tid] = s; ss2[tid] = s2;
    __syncthreads();
    for (int st = 64; st > 0; st >>= 1) {
        if (tid < st) { ss[tid] += ss[tid + st]; ss2[tid] += ss2[tid + st]; }
        __syncthreads();
    }
    if (tid == 0) {
        const float inv_n = 1.0f / 65536.0f;
        float mean = ss[0] * inv_n;
        float var  = ss2[0] * inv_n - mean * mean;
        float gamma, beta;
        float *sd, *bd;
        if (ch < 64) { gamma = gamma_q[ch]; beta = beta_q[ch]; sd = &g_sq[ch]; bd = &g_bq[ch]; }
        else { int c = ch - 64; gamma = gamma_v[c]; beta = beta_v[c]; sd = &g_sv[c]; bd = &g_bv[c]; }
        float sc = gamma * rsqrtf(var + 1e-5f);
        *sd = sc;
        *bd = beta - mean * sc;
    }
}

// ======================================================================
// K3: finalize lambda_c (flash-softmax rescale): M = max_c m_c,
// z = sum_c pz*e^{m-M}, lam = sum_c plam*e^{m-M}; BN fold.
// ======================================================================
__global__ __launch_bounds__(256)
void k_lamc_fin() {
    const int b   = blockIdx.x;
    const int tid = threadIdx.x;

    __shared__ float Msh[16], zinv[16], esc[NCHK][16];

    if (tid < 16) {
        float M = -1e30f;
#pragma unroll
        for (int c = 0; c < NCHK; ++c) M = fmaxf(M, g_pm[b][c][tid]);
        Msh[tid] = M;
    }
    __syncthreads();
    for (int i = tid; i < NCHK * 16; i += 256) {
        int c = i >> 4, kk = i & 15;
        esc[c][kk] = expf(g_pm[b][c][kk] - Msh[kk]);
    }
    __syncthreads();
    if (tid < 16) {
        float z = 0.f;
#pragma unroll
        for (int c = 0; c < NCHK; ++c) z += g_pz[b][c][tid] * esc[c][tid];
        zinv[tid] = 1.0f / z;
    }
    __syncthreads();

#pragma unroll
    for (int i = tid; i < 1024; i += 256) {
        int kk = i >> 6, v = i & 63;
        float s = 0.f;
#pragma unroll
        for (int c = 0; c < NCHK; ++c) s += g_plam[b][c][kk][v] * esc[c][kk];
        g_lamc[(size_t)b * 1024 + i] = g_sv[v] * s * zinv[kk] + g_bv[v];
    }
}

// ======================================================================
// K5: final fused output (R13 version — at FFMA roofline, unchanged).
// ======================================================================
#define VHPITCH 68
#define QP      68
#define SP      28

__global__ __launch_bounds__(512, 2)
void k_final(const float* __restrict__ R, float* __restrict__ out) {
    extern __shared__ float sm[];
    float* q_sm    = sm;
    float* vh_sm   = q_sm + 64 * QP;
    float* s_sm    = vh_sm + 196 * VHPITCH;
    float* lamc_sm = s_sm + 64 * SP;
    float* R_sm    = lamc_sm + 1024;          // [49 t][16 k]

    const int b   = blockIdx.z;
    const int tx0 = blockIdx.x * 8;
    const int ty0 = blockIdx.y * 8;
    const int tid = threadIdx.x;

    for (int i = tid; i < 784; i += 512) {
        int t = i >> 4, kk = i & 15;
        R_sm[i] = R[kk * TAPS + t];
    }
    for (int i = tid; i < 1024; i += 512) lamc_sm[i] = g_lamc[(size_t)b * 1024 + i];

    {
        const float* qb = g_q + (size_t)b * 64 * NPIX;
        for (int idx = tid; idx < 4096; idx += 512) {
            int ch = idx >> 6, lp = idx & 63;
            int ly = lp >> 3,  lx = lp & 7;
            float v = qb[(size_t)ch * NPIX + (ty0 + ly) * IMGW + tx0 + lx];
            q_sm[lp * QP + ch] = v * g_sq[ch] + g_bq[ch];
        }
    }
    {
        const float* vb = g_v + (size_t)b * 64 * NPIX;
        for (int idx = tid; idx < 196 * 64; idx += 512) {
            int ch = idx / 196, hp = idx - ch * 196;
            int hy = hp / 14,   hx = hp - hy * 14;
            int gy = ty0 + hy - PADR, gx = tx0 + hx - PADR;
            float v = 0.f;
            if (gy >= 0 && gy < IMGH && gx >= 0 && gx < IMGW)
                v = vb[(size_t)ch * NPIX + gy * IMGW + gx] * g_sv[ch] + g_bv[ch];
            vh_sm[hp * VHPITCH + ch] = v;
        }
    }
    __syncthreads();

    const int g   = tid >> 6;
    const int pix = tid & 63;
    const int py  = pix >> 3, px = pix & 7;
    const float* qrow = q_sm + pix * QP;
    float* srow = s_sm + pix * SP;

    float acc[4][8];
#pragma unroll
    for (int h = 0; h < 4; ++h)
#pragma unroll
        for (int vi = 0; vi < 8; ++vi) acc[h][vi] = 0.f;

#pragma unroll
    for (int kk0 = 0; kk0 < 16; kk0 += 4) {
        float4 qh[4];
#pragma unroll
        for (int h = 0; h < 4; ++h)
            qh[h] = *(const float4*)(qrow + h * 16 + kk0);
#pragma unroll
        for (int j = 0; j < 4; ++j) {
            const float* lrow = lamc_sm + (kk0 + j) * 64 + g * 8;
            float4 l0 = ((const float4*)lrow)[0];
            float4 l1 = ((const float4*)lrow)[1];
            float lv[8] = {l0.x, l0.y, l0.z, l0.w, l1.x, l1.y, l1.z, l1.w};
            float q0 = (j == 0) ? qh[0].x : (j == 1) ? qh[0].y : (j == 2) ? qh[0].z : qh[0].w;
            float q1 = (j == 0) ? qh[1].x : (j == 1) ? qh[1].y : (j == 2) ? qh[1].z : qh[1].w;
            float q2 = (j == 0) ? qh[2].x : (j == 1) ? qh[2].y : (j == 2) ? qh[2].z : qh[2].w;
            float q3 = (j == 0) ? qh[3].x : (j == 1) ? qh[3].y : (j == 2) ? qh[3].z : qh[3].w;
#pragma unroll
            for (int vi = 0; vi < 8; ++vi) {
                acc[0][vi] += q0 * lv[vi];
                acc[1][vi] += q1 * lv[vi];
                acc[2][vi] += q2 * lv[vi];
                acc[3][vi] += q3 * lv[vi];
            }
        }
    }

    const int hs   = g & 3;
    const int ttlo = (g >> 2) ? 4 : 0;
    const int tthi = (g >> 2) ? 7 : 4;

    for (int dy = 0; dy < RKS; ++dy) {
        __syncthreads();
        {
            float4 qa  = *(const float4*)(qrow + hs * 16 + 0);
            float4 qb4 = *(const float4*)(qrow + hs * 16 + 4);
            float4 qc  = *(const float4*)(qrow + hs * 16 + 8);
            float4 qd  = *(const float4*)(qrow + hs * 16 + 12);
            for (int tt = ttlo; tt < tthi; ++tt) {
                const float4* rr = (const float4*)(R_sm + (dy * RKS + tt) * 16);
                float4 r0 = rr[0], r1 = rr[1], r2 = rr[2], r3 = rr[3];
                float s = qa.x * r0.x + qa.y * r0.y + qa.z * r0.z + qa.w * r0.w
                        + qb4.x * r1.x + qb4.y * r1.y + qb4.z * r1.z + qb4.w * r1.w
                        + qc.x * r2.x + qc.y * r2.y + qc.z * r2.z + qc.w * r2.w
                        + qd.x * r3.x + qd.y * r3.y + qd.z * r3.z + qd.w * r3.w;
                srow[tt * 4 + hs] = s;
            }
        }
        __syncthreads();

#pragma unroll
        for (int dx = 0; dx < RKS; ++dx) {
            const int hp = (py + dy) * 14 + (px + dx);
            const float4* vp = (const float4*)(vh_sm + hp * VHPITCH + g * 8);
            float4 v0 = vp[0], v1 = vp[1];
            float vv[8] = {v0.x, v0.y, v0.z, v0.w, v1.x, v1.y, v1.z, v1.w};
            float4 s4 = *(const float4*)(srow + dx * 4);
#pragma unroll
            for (int vi = 0; vi < 8; ++vi) {
                acc[0][vi] += s4.x * vv[vi];
                acc[1][vi] += s4.y * vv[vi];
                acc[2][vi] += s4.z * vv[vi];
                acc[3][vi] += s4.w * vv[vi];
            }
        }
    }

    const size_t ob = (size_t)b * 256 * NPIX;
    const int gp = (ty0 + py) * IMGW + tx0 + px;
#pragma unroll
    for (int h = 0; h < 4; ++h)
#pragma unroll
        for (int vi = 0; vi < 8; ++vi)
            out[ob + (size_t)(h * 64 + g * 8 + vi) * NPIX + gp] = acc[h][vi];
}

// ======================================================================
extern "C" void kernel_launch(void* const* d_in, const int* in_sizes, int n_in,
                              void* d_out, int out_size) {
    const float* x       = (const float*)d_in[0];
    const float* Wq      = (const float*)d_in[1];
    const float* Wk      = (const float*)d_in[2];
    const float* Wv      = (const float*)d_in[3];
    const float* gamma_q = (const float*)d_in[4];
    const float* beta_q  = (const float*)d_in[5];
    const float* gamma_v = (const float*)d_in[6];
    const float* beta_v  = (const float*)d_in[7];
    const float* R       = (const float*)d_in[8];
    float* out = (float*)d_out;

    cudaFuncSetAttribute(k_proj, cudaFuncAttributeMaxDynamicSharedMemorySize, SM_PROJ);
    const int smemK5 = (64 * QP + 196 * VHPITCH + 64 * SP + 1024 + 784) * (int)sizeof(float);
    cudaFuncSetAttribute(k_final, cudaFuncAttributeMaxDynamicSharedMemorySize, smemK5);

    k_wconv<<<36, 256>>>(Wq, Wk, Wv);
    k_proj<<<dim3(NCHK, BATCH), 256, SM_PROJ>>>(x);
    k_reduce<<<128, 128>>>(gamma_q, beta_q, gamma_v, beta_v);
    k_lamc_fin<<<BATCH, 256>>>();
    k_final<<<dim3(8, 8, BATCH), 512, smemK5>>>(R, out);
}

// round 17
// speedup vs baseline: 1.0489x; 1.0489x over previous
#include <cuda_runtime.h>
#include <cuda_bf16.h>
#include <math.h>

// ---------------- problem constants ----------------
#define BATCH   16
#define CIN     256
#define IMGH    64
#define IMGW    64
#define NPIX    4096
#define HEADS   4
#define DK      16
#define DV      64
#define RKS     7
#define TAPS    49
#define PADR    3

#define N_OUT   144
#define MT      128
#define KCH     64

#define PITCH_A 272
#define PITCH_B 144
#define OFF_AHI 0
#define OFF_ALO (OFF_AHI + KCH * PITCH_A)
#define OFF_BHI (OFF_ALO + KCH * PITCH_A)
#define OFF_BLO (OFF_BHI + N_OUT * PITCH_B)
#define SM_PROJ (OFF_BLO + N_OUT * PITCH_B)
#define DPITCH  132

#define NLC     16        // lamc chunks per batch (256 pixels each)
#define LCP     260       // lamc smem pitch

// ---------------- device scratch ----------------
__device__ float g_q[BATCH * 64 * NPIX];
__device__ float g_k[BATCH * 16 * NPIX];
__device__ float g_v[BATCH * 64 * NPIX];
__device__ float g_sq[64], g_bq[64];
__device__ float g_sv[64], g_bv[64];
__device__ float g_lamc[BATCH * 16 * 64];
__device__ float g_psum[128][512];
__device__ float g_psq [128][512];
__device__ float g_pkmax[BATCH][16][32];
__device__ float g_kmax [BATCH][16];
__device__ __nv_bfloat16 g_wbh[N_OUT * CIN];
__device__ __nv_bfloat16 g_wbl[N_OUT * CIN];
__device__ float g_pz  [BATCH][NLC][16];
__device__ float g_plam[BATCH][NLC][16][64];

// ---------------- helpers ----------------
__device__ __forceinline__ unsigned smem_u32(const void* p) {
    unsigned a;
    asm("{ .reg .u64 t; cvta.to.shared.u64 t, %1; cvt.u32.u64 %0, t; }" : "=r"(a) : "l"(p));
    return a;
}
__device__ __forceinline__ void ldsm_x4t(unsigned addr, unsigned& r0, unsigned& r1,
                                         unsigned& r2, unsigned& r3) {
    asm volatile("ldmatrix.sync.aligned.m8n8.x4.trans.shared.b16 {%0,%1,%2,%3}, [%4];"
                 : "=r"(r0), "=r"(r1), "=r"(r2), "=r"(r3) : "r"(addr));
}
__device__ __forceinline__ void ldsm_x2(unsigned addr, unsigned& r0, unsigned& r1) {
    asm volatile("ldmatrix.sync.aligned.m8n8.x2.shared.b16 {%0,%1}, [%2];"
                 : "=r"(r0), "=r"(r1) : "r"(addr));
}
__device__ __forceinline__ void mma16816(float* d, const unsigned* a, unsigned b0, unsigned b1) {
    asm volatile(
        "mma.sync.aligned.m16n8k16.row.col.f32.bf16.bf16.f32 "
        "{%0,%1,%2,%3}, {%4,%5,%6,%7}, {%8,%9}, {%0,%1,%2,%3};"
        : "+f"(d[0]), "+f"(d[1]), "+f"(d[2]), "+f"(d[3])
        : "r"(a[0]), "r"(a[1]), "r"(a[2]), "r"(a[3]), "r"(b0), "r"(b1));
}
__device__ __forceinline__ void bf_split(float f, unsigned short& hi, unsigned short& lo) {
    __nv_bfloat16 h = __float2bfloat16_rn(f);
    __nv_bfloat16 l = __float2bfloat16_rn(f - __bfloat162float(h));
    hi = __bfloat16_as_ushort(h);
    lo = __bfloat16_as_ushort(l);
}

// ======================================================================
// K0: one-time W -> bf16 hi/lo split.
// ======================================================================
__global__ __launch_bounds__(256)
void k_wconv(const float* __restrict__ Wq, const float* __restrict__ Wk,
             const float* __restrict__ Wv) {
    int idx = blockIdx.x * 256 + threadIdx.x;
    if (idx >= (N_OUT * CIN) / 4) return;
    int o  = idx >> 6;
    int c4 = (idx & 63) * 4;
    const float* wrow = (o < 64) ? (Wq + o * CIN)
                      : (o < 80) ? (Wk + (o - 64) * CIN)
                                 : (Wv + (o - 80) * CIN);
    float4 w = *(const float4*)(wrow + c4);
    unsigned short h[4], l[4];
    bf_split(w.x, h[0], l[0]);
    bf_split(w.y, h[1], l[1]);
    bf_split(w.z, h[2], l[2]);
    bf_split(w.w, h[3], l[3]);
    unsigned long long hp = (unsigned long long)h[0] | ((unsigned long long)h[1] << 16)
                          | ((unsigned long long)h[2] << 32) | ((unsigned long long)h[3] << 48);
    unsigned long long lp = (unsigned long long)l[0] | ((unsigned long long)l[1] << 16)
                          | ((unsigned long long)l[2] << 32) | ((unsigned long long)l[3] << 48);
    *(unsigned long long*)(g_wbh + o * CIN + c4) = hp;
    *(unsigned long long*)(g_wbl + o * CIN + c4) = lp;
}

// ======================================================================
// K1: projection via mma.sync bf16 2-way split + BN-stat partials. (R14)
// ======================================================================
__global__ __launch_bounds__(256)
void k_proj(const float* __restrict__ x) {
    extern __shared__ __align__(16) char smem[];
    const unsigned sb = smem_u32(smem);
    const int tid  = threadIdx.x;
    const int lane = tid & 31;
    const int wid  = tid >> 5;
    const int wm   = wid & 3;
    const int wn   = wid >> 2;
    const int b    = blockIdx.y;
    const int pix0 = blockIdx.x * MT;

    const float* xb = x + (size_t)b * CIN * NPIX + pix0;

    float acc[2][9][4];
#pragma unroll
    for (int mi = 0; mi < 2; ++mi)
#pragma unroll
        for (int ni = 0; ni < 9; ++ni)
#pragma unroll
            for (int r = 0; r < 4; ++r) acc[mi][ni][r] = 0.f;

    const int a_kl = (lane & 7) + ((lane >> 4) << 3);
    const int a_pl = ((lane >> 3) & 1) * 8;
    const int l15  = lane & 15;
    const int b_nl = l15 & 7;
    const int b_kl = ((l15 >> 3) & 1) * 8;

    for (int chunk = 0; chunk < 4; ++chunk) {
        const int c0 = chunk * KCH;

#pragma unroll
        for (int i = 0; i < 8; ++i) {
            int idx = tid + i * 256;
            int cc = idx >> 5, pq = idx & 31;
            float4 xv = *(const float4*)(xb + (size_t)(c0 + cc) * NPIX + pq * 4);
            unsigned short h[4], l[4];
            bf_split(xv.x, h[0], l[0]);
            bf_split(xv.y, h[1], l[1]);
            bf_split(xv.z, h[2], l[2]);
            bf_split(xv.w, h[3], l[3]);
            uint2 hp = make_uint2((unsigned)h[0] | ((unsigned)h[1] << 16),
                                  (unsigned)h[2] | ((unsigned)h[3] << 16));
            uint2 lp = make_uint2((unsigned)l[0] | ((unsigned)l[1] << 16),
                                  (unsigned)l[2] | ((unsigned)l[3] << 16));
            *(uint2*)(smem + OFF_AHI + cc * PITCH_A + pq * 8) = hp;
            *(uint2*)(smem + OFF_ALO + cc * PITCH_A + pq * 8) = lp;
        }
#pragma unroll
        for (int i = 0; i < 5; ++i) {
            int idx = tid + i * 256;
            if (idx < 1152) {
                int o = idx >> 3, j = idx & 7;
                float4 h4 = *(const float4*)((const char*)g_wbh + (o * CIN + c0) * 2 + j * 16);
                float4 l4 = *(const float4*)((const char*)g_wbl + (o * CIN + c0) * 2 + j * 16);
                *(float4*)(smem + OFF_BHI + o * PITCH_B + j * 16) = h4;
                *(float4*)(smem + OFF_BLO + o * PITCH_B + j * 16) = l4;
            }
        }
        __syncthreads();

#pragma unroll
        for (int ks = 0; ks < 4; ++ks) {
            unsigned ahi[2][4], alo[2][4];
#pragma unroll
            for (int mi = 0; mi < 2; ++mi) {
                unsigned aoff = (unsigned)((ks * 16 + a_kl) * PITCH_A
                                           + (wm * 32 + mi * 16 + a_pl) * 2);
                ldsm_x4t(sb + OFF_AHI + aoff, ahi[mi][0], ahi[mi][1], ahi[mi][2], ahi[mi][3]);
                ldsm_x4t(sb + OFF_ALO + aoff, alo[mi][0], alo[mi][1], alo[mi][2], alo[mi][3]);
            }
#pragma unroll
            for (int ni = 0; ni < 9; ++ni) {
                unsigned boff = (unsigned)((wn * 72 + ni * 8 + b_nl) * PITCH_B
                                           + (ks * 16 + b_kl) * 2);
                unsigned bh0, bh1, bl0, bl1;
                ldsm_x2(sb + OFF_BHI + boff, bh0, bh1);
                ldsm_x2(sb + OFF_BLO + boff, bl0, bl1);
#pragma unroll
                for (int mi = 0; mi < 2; ++mi) {
                    mma16816(acc[mi][ni], ahi[mi], bh0, bh1);
                    mma16816(acc[mi][ni], ahi[mi], bl0, bl1);
                    mma16816(acc[mi][ni], alo[mi], bh0, bh1);
                }
            }
        }
        __syncthreads();
    }

    float* dsm = (float*)smem;
#pragma unroll
    for (int mi = 0; mi < 2; ++mi)
#pragma unroll
        for (int ni = 0; ni < 9; ++ni) {
            int o = wn * 72 + ni * 8 + (lane & 3) * 2;
            int p = wm * 32 + mi * 16 + (lane >> 2);
            dsm[o * DPITCH + p]           = acc[mi][ni][0];
            dsm[(o + 1) * DPITCH + p]     = acc[mi][ni][1];
            dsm[o * DPITCH + p + 8]       = acc[mi][ni][2];
            dsm[(o + 1) * DPITCH + p + 8] = acc[mi][ni][3];
        }
    __syncthreads();

    float* qd = g_q + (size_t)b * 64 * NPIX;
    float* kd = g_k + (size_t)b * 16 * NPIX;
    float* vd = g_v + (size_t)b * 64 * NPIX;
#pragma unroll
    for (int i = 0; i < 18; ++i) {
        int idx = tid + i * 256;
        int o = idx >> 5, p4 = idx & 31;
        float4 val = *(const float4*)(dsm + o * DPITCH + p4 * 4);
        float* dst;
        if (o < 64)      dst = qd + (size_t)o * NPIX;
        else if (o < 80) dst = kd + (size_t)(o - 64) * NPIX;
        else             dst = vd + (size_t)(o - 80) * NPIX;
        *(float4*)(dst + pix0 + p4 * 4) = val;
    }

    if (tid < N_OUT) {
        const int o = tid;
        const float* row = dsm + o * DPITCH;
        if (o >= 64 && o < 80) {
            float m = -1e30f;
#pragma unroll
            for (int j = 0; j < 128; j += 4) {
                float4 v = *(const float4*)(row + j);
                m = fmaxf(m, fmaxf(fmaxf(v.x, v.y), fmaxf(v.z, v.w)));
            }
            g_pkmax[b][o - 64][blockIdx.x] = m;
        } else {
            float s = 0.f, s2 = 0.f;
#pragma unroll
            for (int j = 0; j < 128; j += 4) {
                float4 v = *(const float4*)(row + j);
                s  += v.x + v.y + v.z + v.w;
                s2 += v.x * v.x + v.y * v.y + v.z * v.z + v.w * v.w;
            }
            int ch = (o < 64) ? o : (o - 16);
            int slot = b * 32 + blockIdx.x;
            g_psum[ch][slot] = s;
            g_psq [ch][slot] = s2;
        }
    }
}

// ======================================================================
// K2: reduce stat partials -> BN fold params + k row maxes. (R11)
// ======================================================================
__global__ __launch_bounds__(128)
void k_reduce(const float* __restrict__ gamma_q, const float* __restrict__ beta_q,
              const float* __restrict__ gamma_v, const float* __restrict__ beta_v) {
    const int bid = blockIdx.x;
    const int tid = threadIdx.x;

    if (bid < 128) {
        const int ch = bid;
        float s = 0.f, s2 = 0.f;
#pragma unroll
        for (int i = tid; i < 512; i += 128) { s += g_psum[ch][i]; s2 += g_psq[ch][i]; }
        __shared__ float ss[128], ss2[128];
        ss[tid] = s; ss2[tid] = s2;
        __syncthreads();
        for (int st = 64; st > 0; st >>= 1) {
            if (tid < st) { ss[tid] += ss[tid + st]; ss2[tid] += ss2[tid + st]; }
            __syncthreads();
        }
        if (tid == 0) {
            const float inv_n = 1.0f / 65536.0f;
            float mean = ss[0] * inv_n;
            float var  = ss2[0] * inv_n - mean * mean;
            float gamma, beta;
            float *sd, *bd;
            if (ch < 64) { gamma = gamma_q[ch]; beta = beta_q[ch]; sd = &g_sq[ch]; bd = &g_bq[ch]; }
            else { int c = ch - 64; gamma = gamma_v[c]; beta = beta_v[c]; sd = &g_sv[c]; bd = &g_bv[c]; }
            float sc = gamma * rsqrtf(var + 1e-5f);
            *sd = sc;
            *bd = beta - mean * sc;
        }
    } else {
        const int warp = tid >> 5, lane = tid & 31;
        const int pair = (bid - 128) * 4 + warp;
        const int b = pair >> 4, kc = pair & 15;
        float m = g_pkmax[b][kc][lane];
#pragma unroll
        for (int o = 16; o > 0; o >>= 1) m = fmaxf(m, __shfl_down_sync(0xffffffffu, m, o));
        if (lane == 0) g_kmax[b][kc] = m;
    }
}

// ======================================================================
// K3a: lambda_c partials — all 16 k per block, v read ONCE per chunk. (R14)
// grid (NLC=16 chunks of 256 pix, 16 batches), 256 thr, 83KB dyn smem.
// ======================================================================
__global__ __launch_bounds__(256)
void k_lamc_part() {
    extern __shared__ float lsm[];
    float* w_sm = lsm;              // 16 * 260
    float* v_sm = lsm + 16 * LCP;   // 64 * 260

    const int c   = blockIdx.x;     // 0..15
    const int b   = blockIdx.y;
    const int tid = threadIdx.x;
    const int p0  = c * 256;

    const float* kb = g_k + (size_t)b * 16 * NPIX;
    const float* vb = g_v + (size_t)b * 64 * NPIX;

#pragma unroll
    for (int i = 0; i < 16; ++i) {
        int idx = tid + i * 256;
        int kk = idx >> 8, p = idx & 255;
        w_sm[kk * LCP + p] = expf(kb[(size_t)kk * NPIX + p0 + p] - g_kmax[b][kk]);
    }
#pragma unroll
    for (int i = 0; i < 16; ++i) {
        int idx = tid + i * 256;
        int vv = idx >> 6, p4 = idx & 63;
        *(float4*)(v_sm + vv * LCP + p4 * 4) =
            *(const float4*)(vb + (size_t)vv * NPIX + p0 + p4 * 4);
    }
    __syncthreads();

    {
        int warp = tid >> 5, lane = tid & 31;
#pragma unroll
        for (int kk = warp; kk < 16; kk += 8) {
            float s = 0.f;
            for (int p = lane; p < 256; p += 32) s += w_sm[kk * LCP + p];
#pragma unroll
            for (int o = 16; o > 0; o >>= 1) s += __shfl_down_sync(0xffffffffu, s, o);
            if (lane == 0) g_pz[b][c][kk] = s;
        }
    }

    const int kk = tid >> 4;
    const int vq = tid & 15;
    float acc[4] = {0.f, 0.f, 0.f, 0.f};

    for (int p4 = 0; p4 < 64; ++p4) {
        float4 w4 = *(const float4*)(w_sm + kk * LCP + p4 * 4);
#pragma unroll
        for (int m = 0; m < 4; ++m) {
            float4 v4 = *(const float4*)(v_sm + (vq + 16 * m) * LCP + p4 * 4);
            acc[m] += w4.x * v4.x + w4.y * v4.y + w4.z * v4.z + w4.w * v4.w;
        }
    }
#pragma unroll
    for (int m = 0; m < 4; ++m)
        g_plam[b][c][kk][vq + 16 * m] = acc[m];
}

// ======================================================================
// K3b: finalize lambda_c — PARALLEL: one block per (kk, b), 64 thr (v).
// z via broadcast loads; lam sums coalesced across v.
// ======================================================================
__global__ __launch_bounds__(64)
void k_lamc_fin() {
    const int kk = blockIdx.x;
    const int b  = blockIdx.y;
    const int v  = threadIdx.x;

    float z = 0.f;
#pragma unroll
    for (int c = 0; c < NLC; ++c) z += g_pz[b][c][kk];

    float s = 0.f;
#pragma unroll
    for (int c = 0; c < NLC; ++c) s += g_plam[b][c][kk][v];

    g_lamc[(size_t)b * 1024 + kk * 64 + v] = g_sv[v] * s / z + g_bv[v];
}

// ======================================================================
// K5: final fused output (R13 version — at roofline, unchanged).
// ======================================================================
#define VHPITCH 68
#define QP      68
#define SP      28

__global__ __launch_bounds__(512, 2)
void k_final(const float* __restrict__ R, float* __restrict__ out) {
    extern __shared__ float sm[];
    float* q_sm    = sm;
    float* vh_sm   = q_sm + 64 * QP;
    float* s_sm    = vh_sm + 196 * VHPITCH;
    float* lamc_sm = s_sm + 64 * SP;
    float* R_sm    = lamc_sm + 1024;          // [49 t][16 k]

    const int b   = blockIdx.z;
    const int tx0 = blockIdx.x * 8;
    const int ty0 = blockIdx.y * 8;
    const int tid = threadIdx.x;

    for (int i = tid; i < 784; i += 512) {
        int t = i >> 4, kk = i & 15;
        R_sm[i] = R[kk * TAPS + t];
    }
    for (int i = tid; i < 1024; i += 512) lamc_sm[i] = g_lamc[(size_t)b * 1024 + i];

    {
        const float* qb = g_q + (size_t)b * 64 * NPIX;
        for (int idx = tid; idx < 4096; idx += 512) {
            int ch = idx >> 6, lp = idx & 63;
            int ly = lp >> 3,  lx = lp & 7;
            float v = qb[(size_t)ch * NPIX + (ty0 + ly) * IMGW + tx0 + lx];
            q_sm[lp * QP + ch] = v * g_sq[ch] + g_bq[ch];
        }
    }
    {
        const float* vb = g_v + (size_t)b * 64 * NPIX;
        for (int idx = tid; idx < 196 * 64; idx += 512) {
            int ch = idx / 196, hp = idx - ch * 196;
            int hy = hp / 14,   hx = hp - hy * 14;
            int gy = ty0 + hy - PADR, gx = tx0 + hx - PADR;
            float v = 0.f;
            if (gy >= 0 && gy < IMGH && gx >= 0 && gx < IMGW)
                v = vb[(size_t)ch * NPIX + gy * IMGW + gx] * g_sv[ch] + g_bv[ch];
            vh_sm[hp * VHPITCH + ch] = v;
        }
    }
    __syncthreads();

    const int g   = tid >> 6;
    const int pix = tid & 63;
    const int py  = pix >> 3, px = pix & 7;
    const float* qrow = q_sm + pix * QP;
    float* srow = s_sm + pix * SP;

    float acc[4][8];
#pragma unroll
    for (int h = 0; h < 4; ++h)
#pragma unroll
        for (int vi = 0; vi < 8; ++vi) acc[h][vi] = 0.f;

#pragma unroll
    for (int kk0 = 0; kk0 < 16; kk0 += 4) {
        float4 qh[4];
#pragma unroll
        for (int h = 0; h < 4; ++h)
            qh[h] = *(const float4*)(qrow + h * 16 + kk0);
#pragma unroll
        for (int j = 0; j < 4; ++j) {
            const float* lrow = lamc_sm + (kk0 + j) * 64 + g * 8;
            float4 l0 = ((const float4*)lrow)[0];
            float4 l1 = ((const float4*)lrow)[1];
            float lv[8] = {l0.x, l0.y, l0.z, l0.w, l1.x, l1.y, l1.z, l1.w};
            float q0 = (j == 0) ? qh[0].x : (j == 1) ? qh[0].y : (j == 2) ? qh[0].z : qh[0].w;
            float q1 = (j == 0) ? qh[1].x : (j == 1) ? qh[1].y : (j == 2) ? qh[1].z : qh[1].w;
            float q2 = (j == 0) ? qh[2].x : (j == 1) ? qh[2].y : (j == 2) ? qh[2].z : qh[2].w;
            float q3 = (j == 0) ? qh[3].x : (j == 1) ? qh[3].y : (j == 2) ? qh[3].z : qh[3].w;
#pragma unroll
            for (int vi = 0; vi < 8; ++vi) {
                acc[0][vi] += q0 * lv[vi];
                acc[1][vi] += q1 * lv[vi];
                acc[2][vi] += q2 * lv[vi];
                acc[3][vi] += q3 * lv[vi];
            }
        }
    }

    const int hs   = g & 3;
    const int ttlo = (g >> 2) ? 4 : 0;
    const int tthi = (g >> 2) ? 7 : 4;

    for (int dy = 0; dy < RKS; ++dy) {
        __syncthreads();
        {
            float4 qa  = *(const float4*)(qrow + hs * 16 + 0);
            float4 qb4 = *(const float4*)(qrow + hs * 16 + 4);
            float4 qc  = *(const float4*)(qrow + hs * 16 + 8);
            float4 qd  = *(const float4*)(qrow + hs * 16 + 12);
            for (int tt = ttlo; tt < tthi; ++tt) {
                const float4* rr = (const float4*)(R_sm + (dy * RKS + tt) * 16);
                float4 r0 = rr[0], r1 = rr[1], r2 = rr[2], r3 = rr[3];
                float s = qa.x * r0.x + qa.y * r0.y + qa.z * r0.z + qa.w * r0.w
                        + qb4.x * r1.x + qb4.y * r1.y + qb4.z * r1.z + qb4.w * r1.w
                        + qc.x * r2.x + qc.y * r2.y + qc.z * r2.z + qc.w * r2.w
                        + qd.x * r3.x + qd.y * r3.y + qd.z * r3.z + qd.w * r3.w;
                srow[tt * 4 + hs] = s;
            }
        }
        __syncthreads();

#pragma unroll
        for (int dx = 0; dx < RKS; ++dx) {
            const int hp = (py + dy) * 14 + (px + dx);
            const float4* vp = (const float4*)(vh_sm + hp * VHPITCH + g * 8);
            float4 v0 = vp[0], v1 = vp[1];
            float vv[8] = {v0.x, v0.y, v0.z, v0.w, v1.x, v1.y, v1.z, v1.w};
            float4 s4 = *(const float4*)(srow + dx * 4);
#pragma unroll
            for (int vi = 0; vi < 8; ++vi) {
                acc[0][vi] += s4.x * vv[vi];
                acc[1][vi] += s4.y * vv[vi];
                acc[2][vi] += s4.z * vv[vi];
                acc[3][vi] += s4.w * vv[vi];
            }
        }
    }

    const size_t ob = (size_t)b * 256 * NPIX;
    const int gp = (ty0 + py) * IMGW + tx0 + px;
#pragma unroll
    for (int h = 0; h < 4; ++h)
#pragma unroll
        for (int vi = 0; vi < 8; ++vi)
            out[ob + (size_t)(h * 64 + g * 8 + vi) * NPIX + gp] = acc[h][vi];
}

// ======================================================================
extern "C" void kernel_launch(void* const* d_in, const int* in_sizes, int n_in,
                              void* d_out, int out_size) {
    const float* x       = (const float*)d_in[0];
    const float* Wq      = (const float*)d_in[1];
    const float* Wk      = (const float*)d_in[2];
    const float* Wv      = (const float*)d_in[3];
    const float* gamma_q = (const float*)d_in[4];
    const float* beta_q  = (const float*)d_in[5];
    const float* gamma_v = (const float*)d_in[6];
    const float* beta_v  = (const float*)d_in[7];
    const float* R       = (const float*)d_in[8];
    float* out = (float*)d_out;

    cudaFuncSetAttribute(k_proj, cudaFuncAttributeMaxDynamicSharedMemorySize, SM_PROJ);
    const int smemLC = (16 + 64) * LCP * (int)sizeof(float);
    cudaFuncSetAttribute(k_lamc_part, cudaFuncAttributeMaxDynamicSharedMemorySize, smemLC);
    const int smemK5 = (64 * QP + 196 * VHPITCH + 64 * SP + 1024 + 784) * (int)sizeof(float);
    cudaFuncSetAttribute(k_final, cudaFuncAttributeMaxDynamicSharedMemorySize, smemK5);

    k_wconv<<<36, 256>>>(Wq, Wk, Wv);
    k_proj<<<dim3(NPIX / MT, BATCH), 256, SM_PROJ>>>(x);
    k_reduce<<<192, 128>>>(gamma_q, beta_q, gamma_v, beta_v);
    k_lamc_part<<<dim3(NLC, BATCH), 256, smemLC>>>();
    k_lamc_fin<<<dim3(16, BATCH), 64>>>();
    k_final<<<dim3(8, 8, BATCH), 512, smemK5>>>(R, out);
}